// round 1
// baseline (speedup 1.0000x reference)
#include <cuda_runtime.h>
#include <cuda_bf16.h>

// Output = C_total * conv3x3(inp, k), where C_total is the closed-form scalar of the
// linear LIF recurrence (nonlinearities provably inactive for I in [0,9)).

#define TW   128   // threads per block
#define ROWS 15    // output rows per block

__global__ __launch_bounds__(TW)
void snn_conv_kernel(const float* __restrict__ inp,
                     const float* __restrict__ kw,
                     float* __restrict__ out,
                     float cscale)
{
    const int W  = 512;   // input width/height
    const int OW = 510;   // output width/height
    const int OH = 510;

    const int n  = blockIdx.y;
    const int y0 = blockIdx.x * ROWS;
    const int x0 = threadIdx.x * 4;          // first output column for this thread

    // 3x3 weights (k is (3,3,1,1) row-major -> 9 floats)
    const float k00 = kw[0], k01 = kw[1], k02 = kw[2];
    const float k10 = kw[3], k11 = kw[4], k12 = kw[5];
    const float k20 = kw[6], k21 = kw[7], k22 = kw[8];

    const float* base  = inp + (size_t)n * W * W;
    float*       obase = out + (size_t)n * OW * OH;

    const bool hasb = (x0 + 4) < W;          // guard the 2-float tail load (only t=127 lacks it)

    // Sliding 3-row register window: each row = 6 floats (float4 + float2)
    float4 a0, a1;
    float2 b0, b1;
    {
        const float* r0 = base + (size_t)y0 * W + x0;
        const float* r1 = r0 + W;
        a0 = *(const float4*)r0;
        a1 = *(const float4*)r1;
        b0 = hasb ? *(const float2*)(r0 + 4) : make_float2(0.f, 0.f);
        b1 = hasb ? *(const float2*)(r1 + 4) : make_float2(0.f, 0.f);
    }

#pragma unroll
    for (int r = 0; r < ROWS; r++) {
        const int y = y0 + r;
        if (y >= OH) break;

        const float* r2p = base + (size_t)(y + 2) * W + x0;
        float4 a2 = *(const float4*)r2p;
        float2 b2 = hasb ? *(const float2*)(r2p + 4) : make_float2(0.f, 0.f);

        float s0 = k00*a0.x + k01*a0.y + k02*a0.z
                 + k10*a1.x + k11*a1.y + k12*a1.z
                 + k20*a2.x + k21*a2.y + k22*a2.z;
        float s1 = k00*a0.y + k01*a0.z + k02*a0.w
                 + k10*a1.y + k11*a1.z + k12*a1.w
                 + k20*a2.y + k21*a2.z + k22*a2.w;
        float s2 = k00*a0.z + k01*a0.w + k02*b0.x
                 + k10*a1.z + k11*a1.w + k12*b1.x
                 + k20*a2.z + k21*a2.w + k22*b2.x;
        float s3 = k00*a0.w + k01*b0.x + k02*b0.y
                 + k10*a1.w + k11*b1.x + k12*b1.y
                 + k20*a2.w + k21*b2.x + k22*b2.y;

        s0 *= cscale; s1 *= cscale; s2 *= cscale; s3 *= cscale;

        float* orow = obase + (size_t)y * OW + x0;
        if (x0 + 3 < OW) {
            // output pitch 510 -> only 8B alignment guaranteed (x0 even, row base even)
            *(float2*)(orow)     = make_float2(s0, s1);
            *(float2*)(orow + 2) = make_float2(s2, s3);
        } else if (x0 < OW) {
            // tail thread: exactly 2 valid columns (OW % 4 == 2)
            *(float2*)(orow)     = make_float2(s0, s1);
        }

        a0 = a1; b0 = b1;
        a1 = a2; b1 = b2;
    }
}

extern "C" void kernel_launch(void* const* d_in, const int* in_sizes, int n_in,
                              void* d_out, int out_size)
{
    const float* inp = (const float*)d_in[0];   // (64,512,512,1) fp32
    const float* k   = (const float*)d_in[1];   // (3,3,1,1) fp32
    float* out = (float*)d_out;                 // (64,510,510,1) fp32

    // Closed-form LIF coefficient, computed in double on host (runs once at capture).
    // v0 = step(0,1); then 999 iterations of v = v + (-v + R)/(R*C)*DT; vt = (v+vt)/1000.
    // All clamps are identities for I=1 (v stays < 1 << 14).
    const double DT = 0.01, R = 3000.0, C = 10.0, NS = 1000.0;
    double v  = (R * 1.0) / (R * C) * DT;   // v0 = 1e-3
    double vt = v;
    for (int i = 0; i < 999; i++) {
        v  = v + (-v + R * 1.0) / (R * C) * DT;
        vt = (v + vt) / NS;
    }
    const float cscale = (float)vt;         // ~1.0008e-3

    dim3 block(TW);
    dim3 grid((510 + ROWS - 1) / ROWS, 64);
    snn_conv_kernel<<<grid, block>>>(inp, k, out, cscale);
}

// round 3
// speedup vs baseline: 1.0556x; 1.0556x over previous
#include <cuda_runtime.h>
#include <cuda_bf16.h>

// Output = C_total * conv3x3(inp, k): the 1000-step LIF recurrence is linear for
// I in [0,9) (spike/reset clamps provably inactive), so it collapses to a scalar.

#define TW   128   // threads per block (each handles 4 output columns)
#define ROWS 15    // output rows per block; 510 = 34 * 15 exactly

struct RowRegs { float4 a; float2 b; };

__device__ __forceinline__ RowRegs load_row(const float* p, bool hasb)
{
    RowRegs r;
    r.a = *(const float4*)p;
    r.b = hasb ? *(const float2*)(p + 4) : make_float2(0.f, 0.f);
    return r;
}

__global__ __launch_bounds__(TW, 4)
void snn_conv_kernel(const float* __restrict__ inp,
                     const float* __restrict__ kw,
                     float* __restrict__ out,
                     float cscale)
{
    const int W  = 512;   // input width/height
    const int OW = 510;   // output width/height

    const int n  = blockIdx.y;
    const int y0 = blockIdx.x * ROWS;        // y0 <= 495; rows y0..y0+16 all < 512
    const int x0 = threadIdx.x * 4;          // first output column for this thread

    // 3x3 weights with the LIF scalar folded in (removes per-pixel scaling)
    const float k00 = kw[0]*cscale, k01 = kw[1]*cscale, k02 = kw[2]*cscale;
    const float k10 = kw[3]*cscale, k11 = kw[4]*cscale, k12 = kw[5]*cscale;
    const float k20 = kw[6]*cscale, k21 = kw[7]*cscale, k22 = kw[8]*cscale;

    const float* base  = inp + (size_t)n * W * W + x0;
    float*       obase = out + (size_t)n * OW * OW + x0;

    const bool hasb     = (x0 + 4) < W;      // only thread 127 lacks the 2-float tail
    const bool fullcols = (x0 + 3) < OW;     // thread 127 writes only 2 valid cols

    // 5-row register window, 2-deep load pipeline:
    // while computing output row r (inputs r..r+2), input row r+4 is in flight.
    RowRegs L[5];
#pragma unroll
    for (int i = 0; i < 4; i++)
        L[i] = load_row(base + (size_t)(y0 + i) * W, hasb);

#pragma unroll
    for (int r = 0; r < ROWS; r++) {
        // issue the prefetch FIRST so it overlaps this iteration's FMAs + store
        if (r + 4 <= ROWS + 1)
            L[(r + 4) % 5] = load_row(base + (size_t)(y0 + r + 4) * W, hasb);

        const RowRegs& t = L[(r + 0) % 5];
        const RowRegs& m = L[(r + 1) % 5];
        const RowRegs& d = L[(r + 2) % 5];

        float s0 = k00*t.a.x + k01*t.a.y + k02*t.a.z
                 + k10*m.a.x + k11*m.a.y + k12*m.a.z
                 + k20*d.a.x + k21*d.a.y + k22*d.a.z;
        float s1 = k00*t.a.y + k01*t.a.z + k02*t.a.w
                 + k10*m.a.y + k11*m.a.z + k12*m.a.w
                 + k20*d.a.y + k21*d.a.z + k22*d.a.w;
        float s2 = k00*t.a.z + k01*t.a.w + k02*t.b.x
                 + k10*m.a.z + k11*m.a.w + k12*m.b.x
                 + k20*d.a.z + k21*d.a.w + k22*d.b.x;
        float s3 = k00*t.a.w + k01*t.b.x + k02*t.b.y
                 + k10*m.a.w + k11*m.b.x + k12*m.b.y
                 + k20*d.a.w + k21*d.b.x + k22*d.b.y;

        float* orow = obase + (size_t)(y0 + r) * OW;
        // output pitch 510 -> only 8B alignment guaranteed
        *(float2*)(orow) = make_float2(s0, s1);
        if (fullcols)
            *(float2*)(orow + 2) = make_float2(s2, s3);
    }
}

extern "C" void kernel_launch(void* const* d_in, const int* in_sizes, int n_in,
                              void* d_out, int out_size)
{
    const float* inp = (const float*)d_in[0];   // (64,512,512,1) fp32
    const float* k   = (const float*)d_in[1];   // (3,3,1,1) fp32
    float* out = (float*)d_out;                 // (64,510,510,1) fp32

    // Closed-form LIF coefficient (double precision, host, once per capture).
    const double DT = 0.01, R = 3000.0, C = 10.0, NS = 1000.0;
    double v  = (R * 1.0) / (R * C) * DT;   // v0 = 1e-3
    double vt = v;
    for (int i = 0; i < 999; i++) {
        v  = v + (-v + R * 1.0) / (R * C) * DT;
        vt = (v + vt) / NS;
    }
    const float cscale = (float)vt;         // ~1.0008e-3

    dim3 block(TW);
    dim3 grid(510 / ROWS, 64);              // 34 x 64 = 2176 blocks
    snn_conv_kernel<<<grid, block>>>(inp, k, out, cscale);
}